// round 1
// baseline (speedup 1.0000x reference)
#include <cuda_runtime.h>
#include <math.h>

// Problem sizes (fixed by the reference)
#define NN 4096
#define FF 2048
#define BB 2048

// Scratch for the 4 gate pre-activations (z_i, z_f, z_g, z_o), 4 x 33.5 MB.
// __device__ globals are the allowed scratch mechanism (no cudaMalloc).
static __device__ float g_z0[(size_t)NN * FF];
static __device__ float g_z1[(size_t)NN * FF];
static __device__ float g_z2[(size_t)NN * FF];
static __device__ float g_z3[(size_t)NN * FF];

// ---------------------------------------------------------------------------
// Gate GEMM: Z = A1 @ W1 + A2 @ W2 + bias
//   A1 = h0        [NN, FF]  row-major
//   W1 = W*_h      [FF, FF]  row-major (K x N)
//   A2 = behavior  [NN, BB]  row-major
//   W2 = W*_x      [BB, FF]  row-major (K x N)
// Tiling: 128x128 block tile, BK=16, 256 threads, 8x8 per-thread microtile.
// ---------------------------------------------------------------------------
__global__ __launch_bounds__(256, 2)
void gate_gemm_kernel(const float* __restrict__ A1,
                      const float* __restrict__ W1,
                      const float* __restrict__ A2,
                      const float* __restrict__ W2,
                      const float* __restrict__ bias,
                      int gate)
{
    constexpr int BM = 128, BN = 128, BK = 16;

    __shared__ __align__(16) float As[BK][BM];   // A tile, transposed (k-major rows)
    __shared__ __align__(16) float Bs[BK][BN];   // W tile

    float* __restrict__ Z =
        (gate == 0) ? g_z0 : (gate == 1) ? g_z1 : (gate == 2) ? g_z2 : g_z3;

    const int n0 = blockIdx.x * BN;   // output column (over FF)
    const int m0 = blockIdx.y * BM;   // output row    (over NN)
    const int t  = threadIdx.x;       // 0..255
    const int tx = t & 15;            // 0..15  -> n sub-tile
    const int ty = t >> 4;            // 0..15  -> m sub-tile

    float acc[8][8];
#pragma unroll
    for (int i = 0; i < 8; i++)
#pragma unroll
        for (int j = 0; j < 8; j++) acc[i][j] = 0.0f;

    // Two passes over the two K-segments: (h0, W_h, K=FF) then (behavior, W_x, K=BB)
#pragma unroll 1
    for (int pass = 0; pass < 2; pass++) {
        const float* __restrict__ A = pass ? A2 : A1;
        const float* __restrict__ W = pass ? W2 : W1;
        const int K = pass ? BB : FF;

#pragma unroll 1
        for (int kt = 0; kt < K; kt += BK) {
            // ---- Load A tile (BM x BK), transposed into As[BK][BM] ----
            // 512 float4 total -> 2 per thread
#pragma unroll
            for (int i = 0; i < 2; i++) {
                int idx = t * 2 + i;          // 0..511
                int row = idx >> 2;           // 0..127 (m within tile)
                int c4  = idx & 3;            // which float4 in the 16-wide k slab
                float4 v = *(const float4*)(A + (size_t)(m0 + row) * K + kt + c4 * 4);
                As[c4 * 4 + 0][row] = v.x;
                As[c4 * 4 + 1][row] = v.y;
                As[c4 * 4 + 2][row] = v.z;
                As[c4 * 4 + 3][row] = v.w;
            }
            // ---- Load W tile (BK x BN) ----
#pragma unroll
            for (int i = 0; i < 2; i++) {
                int idx = t * 2 + i;          // 0..511
                int row = idx >> 5;           // 0..15 (k within tile)
                int c   = idx & 31;           // 0..31 (float4 column)
                *(float4*)(&Bs[row][c * 4]) =
                    *(const float4*)(W + (size_t)(kt + row) * FF + n0 + c * 4);
            }
            __syncthreads();

            // ---- FFMA microkernel ----
#pragma unroll
            for (int k = 0; k < BK; k++) {
                float4 a0 = *(const float4*)&As[k][ty * 8];
                float4 a1 = *(const float4*)&As[k][ty * 8 + 4];
                float4 b0 = *(const float4*)&Bs[k][tx * 8];
                float4 b1 = *(const float4*)&Bs[k][tx * 8 + 4];
                float ra[8] = {a0.x, a0.y, a0.z, a0.w, a1.x, a1.y, a1.z, a1.w};
                float rb[8] = {b0.x, b0.y, b0.z, b0.w, b1.x, b1.y, b1.z, b1.w};
#pragma unroll
                for (int i = 0; i < 8; i++)
#pragma unroll
                    for (int j = 0; j < 8; j++)
                        acc[i][j] = fmaf(ra[i], rb[j], acc[i][j]);
            }
            __syncthreads();
        }
    }

    // ---- Epilogue: add bias, store z ----
#pragma unroll
    for (int i = 0; i < 8; i++) {
        int m = m0 + ty * 8 + i;
#pragma unroll
        for (int j = 0; j < 8; j += 4) {
            int n = n0 + tx * 8 + j;
            float4 v;
            v.x = acc[i][j + 0] + bias[n + 0];
            v.y = acc[i][j + 1] + bias[n + 1];
            v.z = acc[i][j + 2] + bias[n + 2];
            v.w = acc[i][j + 3] + bias[n + 3];
            *(float4*)(Z + (size_t)m * FF + n) = v;
        }
    }
}

// ---------------------------------------------------------------------------
// LSTM elementwise epilogue:
//   i = sigmoid(z0); f = sigmoid(z1); g = tanh(z2); o = sigmoid(z3)
//   c = f*c0 + i*g;  h = o * tanh(c)
// ---------------------------------------------------------------------------
__device__ __forceinline__ float sigf(float x) {
    return 1.0f / (1.0f + expf(-x));
}

__global__ __launch_bounds__(256)
void lstm_epilogue_kernel(const float* __restrict__ c0, float* __restrict__ h)
{
    size_t idx = (size_t)blockIdx.x * blockDim.x + threadIdx.x;  // float4 index
    const size_t total4 = (size_t)NN * FF / 4;
    if (idx >= total4) return;

    float4 zi = ((const float4*)g_z0)[idx];
    float4 zf = ((const float4*)g_z1)[idx];
    float4 zg = ((const float4*)g_z2)[idx];
    float4 zo = ((const float4*)g_z3)[idx];
    float4 c0v = ((const float4*)c0)[idx];

    float4 out;
    {
        float i = sigf(zi.x), f = sigf(zf.x), g = tanhf(zg.x), o = sigf(zo.x);
        float c = f * c0v.x + i * g;
        out.x = o * tanhf(c);
    }
    {
        float i = sigf(zi.y), f = sigf(zf.y), g = tanhf(zg.y), o = sigf(zo.y);
        float c = f * c0v.y + i * g;
        out.y = o * tanhf(c);
    }
    {
        float i = sigf(zi.z), f = sigf(zf.z), g = tanhf(zg.z), o = sigf(zo.z);
        float c = f * c0v.z + i * g;
        out.z = o * tanhf(c);
    }
    {
        float i = sigf(zi.w), f = sigf(zf.w), g = tanhf(zg.w), o = sigf(zo.w);
        float c = f * c0v.w + i * g;
        out.w = o * tanhf(c);
    }
    ((float4*)h)[idx] = out;
}

// ---------------------------------------------------------------------------
// kernel_launch — graph-capturable: kernel launches only, no sync, no alloc.
// Input order (metadata): behavior, h0, c0,
//   Wi_h, Wi_x, bi, Wf_h, Wf_x, bf, Wg_h, Wg_x, bg, Wo_h, Wo_x, bo
// ---------------------------------------------------------------------------
extern "C" void kernel_launch(void* const* d_in, const int* in_sizes, int n_in,
                              void* d_out, int out_size)
{
    const float* behavior = (const float*)d_in[0];
    const float* h0       = (const float*)d_in[1];
    const float* c0       = (const float*)d_in[2];
    const float* Wi_h = (const float*)d_in[3];
    const float* Wi_x = (const float*)d_in[4];
    const float* bi   = (const float*)d_in[5];
    const float* Wf_h = (const float*)d_in[6];
    const float* Wf_x = (const float*)d_in[7];
    const float* bf   = (const float*)d_in[8];
    const float* Wg_h = (const float*)d_in[9];
    const float* Wg_x = (const float*)d_in[10];
    const float* bg   = (const float*)d_in[11];
    const float* Wo_h = (const float*)d_in[12];
    const float* Wo_x = (const float*)d_in[13];
    const float* bo   = (const float*)d_in[14];
    float* h = (float*)d_out;

    dim3 grid(FF / 128, NN / 128);   // 16 x 32 blocks
    dim3 block(256);

    gate_gemm_kernel<<<grid, block>>>(h0, Wi_h, behavior, Wi_x, bi, 0);
    gate_gemm_kernel<<<grid, block>>>(h0, Wf_h, behavior, Wf_x, bf, 1);
    gate_gemm_kernel<<<grid, block>>>(h0, Wg_h, behavior, Wg_x, bg, 2);
    gate_gemm_kernel<<<grid, block>>>(h0, Wo_h, behavior, Wo_x, bo, 3);

    const size_t total4 = (size_t)NN * FF / 4;
    int eblocks = (int)((total4 + 255) / 256);
    lstm_epilogue_kernel<<<eblocks, 256>>>(c0, h);
}

// round 3
// speedup vs baseline: 3.3470x; 3.3470x over previous
#include <cuda_runtime.h>
#include <cuda_fp16.h>
#include <cstdint>
#include <math.h>

#define NN   4096
#define FFD  2048
#define NTOT 8192   // 4 gates x 2048, concatenated in N
#define KTOT 4096   // concat K: [h0 (2048) | behavior (2048)]

// ---------------- device scratch (no cudaMalloc allowed) -------------------
static __device__ __half g_Ah[(size_t)NN * KTOT];       // 33.5MB  A hi (fp16)
static __device__ __half g_Al[(size_t)NN * KTOT];       // 33.5MB  A lo (fp16)
static __device__ __half g_W [(size_t)NTOT * KTOT];     // 67MB    W^T fp16, [n_global][k]
static __device__ float  g_z [(size_t)4 * NN * FFD];    // 134MB   gate pre-activations

// ---------------- helpers ---------------------------------------------------
__device__ __forceinline__ uint32_t smem_u32(const void* p) {
    uint32_t a;
    asm("{ .reg .u64 t; cvta.to.shared.u64 t, %1; cvt.u32.u64 %0, t; }"
        : "=r"(a) : "l"(p));
    return a;
}
__device__ __forceinline__ void cpa16(uint32_t s, const void* g) {
    asm volatile("cp.async.cg.shared.global [%0], [%1], 16;" :: "r"(s), "l"(g));
}
#define CPA_COMMIT() asm volatile("cp.async.commit_group;" ::: "memory")
#define CPA_WAIT2()  asm volatile("cp.async.wait_group 2;" ::: "memory")

__device__ __forceinline__ void ldsm4(uint32_t* r, uint32_t addr) {
    asm volatile("ldmatrix.sync.aligned.m8n8.x4.shared.b16 {%0,%1,%2,%3}, [%4];"
                 : "=r"(r[0]), "=r"(r[1]), "=r"(r[2]), "=r"(r[3]) : "r"(addr));
}
__device__ __forceinline__ void mma16816(float* c, const uint32_t* a, const uint32_t* b) {
    asm volatile("mma.sync.aligned.m16n8k16.row.col.f32.f16.f16.f32 "
                 "{%0,%1,%2,%3}, {%4,%5,%6,%7}, {%8,%9}, {%0,%1,%2,%3};"
                 : "+f"(c[0]), "+f"(c[1]), "+f"(c[2]), "+f"(c[3])
                 : "r"(a[0]), "r"(a[1]), "r"(a[2]), "r"(a[3]),
                   "r"(b[0]), "r"(b[1]));
}

// ---------------- pre-pass 1: A = [h0 | behavior] -> fp16 hi/lo -------------
__global__ __launch_bounds__(256)
void conv_A_kernel(const float* __restrict__ h0, const float* __restrict__ beh) {
    size_t e = ((size_t)blockIdx.x * 256 + threadIdx.x) * 4;
    int m = (int)(e >> 12);
    int k = (int)(e & 4095);
    const float* src = (k < 2048) ? (h0 + (size_t)m * 2048 + k)
                                  : (beh + (size_t)m * 2048 + (k - 2048));
    float4 v = *(const float4*)src;
    float x[4] = {v.x, v.y, v.z, v.w};
    __half hv[4], lv[4];
#pragma unroll
    for (int i = 0; i < 4; i++) {
        hv[i] = __float2half_rn(x[i]);
        lv[i] = __float2half_rn(x[i] - __half2float(hv[i]));
    }
    __half2* dh = (__half2*)(g_Ah + e);
    __half2* dl = (__half2*)(g_Al + e);
    dh[0] = __halves2half2(hv[0], hv[1]);
    dh[1] = __halves2half2(hv[2], hv[3]);
    dl[0] = __halves2half2(lv[0], lv[1]);
    dl[1] = __halves2half2(lv[2], lv[3]);
}

// ---------------- pre-pass 2: W transpose -> fp16 [n_global][k] -------------
// src matrices are [K=2048][N=2048] row-major; dst g_W[(g*2048+n)*4096 + isx*2048 + k]
__global__ __launch_bounds__(256)
void conv_W_kernel(const float* Wi_h, const float* Wi_x,
                   const float* Wf_h, const float* Wf_x,
                   const float* Wg_h, const float* Wg_x,
                   const float* Wo_h, const float* Wo_x) {
    const float* srcs[8] = {Wi_h, Wi_x, Wf_h, Wf_x, Wg_h, Wg_x, Wo_h, Wo_x};
    int z = blockIdx.z;
    int g = z >> 1, isx = z & 1;
    const float* __restrict__ src = srcs[z];

    __shared__ float t[32][33];
    int k0 = blockIdx.x * 32, n0 = blockIdx.y * 32;
    int tx = threadIdx.x, ty = threadIdx.y;
#pragma unroll
    for (int i = 0; i < 4; i++)
        t[ty + i * 8][tx] = src[(size_t)(k0 + ty + i * 8) * 2048 + n0 + tx];
    __syncthreads();
#pragma unroll
    for (int i = 0; i < 4; i++) {
        int n = n0 + ty + i * 8;
        int k = k0 + tx;
        float x = t[tx][ty + i * 8];
        g_W[((size_t)g * FFD + n) * KTOT + isx * 2048 + k] = __float2half_rn(x);
    }
}

// ---------------- main GEMM: z = A @ W^T (2-pass fp16 split-A) --------------
// BM=128, BN=256, BK=64, 3 stages, 256 threads, warp tile 64x64 (2m x 4n)
static constexpr int AH_OFF   = 0;        // 128 rows x 128B = 16KB
static constexpr int AL_OFF   = 16384;    // 16KB
static constexpr int WP_OFF   = 32768;    // 256 rows x 128B = 32KB
static constexpr int STAGE_SZ = 65536;    // 64KB
static constexpr int SMEM_TOTAL = 3 * STAGE_SZ;  // 192KB

__device__ __forceinline__ void fill_stage(uint32_t sb, int m0, int n0, int kb, int tid) {
#pragma unroll
    for (int i = 0; i < 4; i++) {               // A hi + lo: 1024 16B units each
        int u = tid + i * 256;
        int row = u >> 3, cu = u & 7;
        uint32_t sw = (uint32_t)(row * 128 + ((cu ^ (row & 7)) << 4));
        size_t go = (size_t)(m0 + row) * KTOT + kb + cu * 8;
        cpa16(sb + AH_OFF + sw, g_Ah + go);
        cpa16(sb + AL_OFF + sw, g_Al + go);
    }
#pragma unroll
    for (int i = 0; i < 8; i++) {               // W: 2048 16B units
        int u = tid + i * 256;
        int row = u >> 3, cu = u & 7;
        uint32_t sw = (uint32_t)(row * 128 + ((cu ^ (row & 7)) << 4));
        size_t go = (size_t)(n0 + row) * KTOT + kb + cu * 8;
        cpa16(sb + WP_OFF + sw, g_W + go);
    }
}

__global__ __launch_bounds__(256, 1)
void gemm_kernel() {
    extern __shared__ __align__(1024) char smem[];
    const uint32_t base = smem_u32(smem);
    const int tid = threadIdx.x;
    const int wid = tid >> 5;
    const int lane = tid & 31;
    const int warp_m = wid & 1;    // 2 warps over M (64 rows each)
    const int warp_n = wid >> 1;   // 4 warps over N (64 cols each)
    const int m0 = blockIdx.y * 128;
    const int n0 = blockIdx.x * 256;

    const int quad = lane >> 3, rr = lane & 7;
    // ldmatrix lane->address roles
    const int rowA_base = warp_m * 64 + (quad & 1) * 8 + rr;  // + mi*16
    const int chA = quad >> 1;
    const int rowB_base = warp_n * 64 + (quad >> 1) * 8 + rr; // + nh*16
    const int chB = quad & 1;

    float acc[4][8][4];
#pragma unroll
    for (int mi = 0; mi < 4; mi++)
#pragma unroll
        for (int ni = 0; ni < 8; ni++)
#pragma unroll
            for (int q = 0; q < 4; q++) acc[mi][ni][q] = 0.0f;

    // prologue: chunks 0,1
    fill_stage(base + 0 * STAGE_SZ, m0, n0, 0, tid);  CPA_COMMIT();
    fill_stage(base + 1 * STAGE_SZ, m0, n0, 64, tid); CPA_COMMIT();

    const int NCH = KTOT / 64;  // 64
#pragma unroll 1
    for (int c = 0; c < NCH; c++) {
        if (c + 2 < NCH)
            fill_stage(base + ((c + 2) % 3) * STAGE_SZ, m0, n0, (c + 2) * 64, tid);
        CPA_COMMIT();
        CPA_WAIT2();
        __syncthreads();

        const uint32_t sb = base + (c % 3) * STAGE_SZ;
        const uint32_t Ab = sb + AH_OFF, Lb = sb + AL_OFF, Wb = sb + WP_OFF;

#pragma unroll
        for (int ks = 0; ks < 4; ks++) {
            uint32_t b[16], ah[16], al[16];
#pragma unroll
            for (int nh = 0; nh < 4; nh++) {
                int row = rowB_base + nh * 16;
                int u = ks * 2 + chB;
                ldsm4(&b[nh * 4], Wb + row * 128 + ((u ^ (row & 7)) << 4));
            }
#pragma unroll
            for (int mi = 0; mi < 4; mi++) {
                int row = rowA_base + mi * 16;
                int u = ks * 2 + chA;
                uint32_t sw = row * 128 + ((u ^ (row & 7)) << 4);
                ldsm4(&ah[mi * 4], Ab + sw);
                ldsm4(&al[mi * 4], Lb + sw);
            }
            // pass 1: A_hi x W
#pragma unroll
            for (int mi = 0; mi < 4; mi++)
#pragma unroll
                for (int ni = 0; ni < 8; ni++)
                    mma16816(acc[mi][ni], &ah[mi * 4],
                             &b[(ni >> 1) * 4 + (ni & 1) * 2]);
            // pass 2: A_lo x W (reuses W fragments)
#pragma unroll
            for (int mi = 0; mi < 4; mi++)
#pragma unroll
                for (int ni = 0; ni < 8; ni++)
                    mma16816(acc[mi][ni], &al[mi * 4],
                             &b[(ni >> 1) * 4 + (ni & 1) * 2]);
        }
        __syncthreads();
    }

    // ---- store z tile (raw pre-activation, bias added in epilogue) ----
    const int gate = n0 >> 11;
    float* __restrict__ Z = g_z + (size_t)gate * NN * FFD;
    const int ncol0 = (n0 & 2047) + warp_n * 64 + (lane & 3) * 2;
    const int row0  = m0 + warp_m * 64 + (lane >> 2);
#pragma unroll
    for (int mi = 0; mi < 4; mi++) {
        int r = row0 + mi * 16;
#pragma unroll
        for (int ni = 0; ni < 8; ni++) {
            int cc = ncol0 + ni * 8;
            *(float2*)(Z + (size_t)r * FFD + cc) =
                make_float2(acc[mi][ni][0], acc[mi][ni][1]);
            *(float2*)(Z + (size_t)(r + 8) * FFD + cc) =
                make_float2(acc[mi][ni][2], acc[mi][ni][3]);
        }
    }
}

// ---------------- LSTM elementwise epilogue ---------------------------------
__global__ __launch_bounds__(256)
void lstm_epilogue_kernel(const float* __restrict__ c0, float* __restrict__ h,
                          const float* __restrict__ bi, const float* __restrict__ bf,
                          const float* __restrict__ bg, const float* __restrict__ bo)
{
    size_t idx = (size_t)blockIdx.x * blockDim.x + threadIdx.x;  // float4 index
    size_t e = idx * 4;
    int col = (int)(e & (FFD - 1));

    const size_t GS = (size_t)NN * FFD;
    float4 zi = *(const float4*)(g_z + 0 * GS + e);
    float4 zf = *(const float4*)(g_z + 1 * GS + e);
    float4 zg = *(const float4*)(g_z + 2 * GS + e);
    float4 zo = *(const float4*)(g_z + 3 * GS + e);
    float4 bvi = *(const float4*)(bi + col);
    float4 bvf = *(const float4*)(bf + col);
    float4 bvg = *(const float4*)(bg + col);
    float4 bvo = *(const float4*)(bo + col);
    float4 c0v = *(const float4*)(c0 + e);

    float vi[4] = {zi.x + bvi.x, zi.y + bvi.y, zi.z + bvi.z, zi.w + bvi.w};
    float vf[4] = {zf.x + bvf.x, zf.y + bvf.y, zf.z + bvf.z, zf.w + bvf.w};
    float vg[4] = {zg.x + bvg.x, zg.y + bvg.y, zg.z + bvg.z, zg.w + bvg.w};
    float vo[4] = {zo.x + bvo.x, zo.y + bvo.y, zo.z + bvo.z, zo.w + bvo.w};
    float cv[4] = {c0v.x, c0v.y, c0v.z, c0v.w};

    float out[4];
#pragma unroll
    for (int j = 0; j < 4; j++) {
        float ig = 1.0f / (1.0f + expf(-vi[j]));
        float fg = 1.0f / (1.0f + expf(-vf[j]));
        float gg = tanhf(vg[j]);
        float og = 1.0f / (1.0f + expf(-vo[j]));
        float cc = fg * cv[j] + ig * gg;
        out[j] = og * tanhf(cc);
    }
    float4 o4 = make_float4(out[0], out[1], out[2], out[3]);
    *(float4*)(h + e) = o4;
}

// ---------------- kernel_launch ---------------------------------------------
// inputs: behavior, h0, c0, Wi_h, Wi_x, bi, Wf_h, Wf_x, bf, Wg_h, Wg_x, bg,
//         Wo_h, Wo_x, bo
extern "C" void kernel_launch(void* const* d_in, const int* in_sizes, int n_in,
                              void* d_out, int out_size)
{
    const float* behavior = (const float*)d_in[0];
    const float* h0       = (const float*)d_in[1];
    const float* c0       = (const float*)d_in[2];
    const float* Wi_h = (const float*)d_in[3];
    const float* Wi_x = (const float*)d_in[4];
    const float* bi   = (const float*)d_in[5];
    const float* Wf_h = (const float*)d_in[6];
    const float* Wf_x = (const float*)d_in[7];
    const float* bf   = (const float*)d_in[8];
    const float* Wg_h = (const float*)d_in[9];
    const float* Wg_x = (const float*)d_in[10];
    const float* bg   = (const float*)d_in[11];
    const float* Wo_h = (const float*)d_in[12];
    const float* Wo_x = (const float*)d_in[13];
    const float* bo   = (const float*)d_in[14];
    float* hout = (float*)d_out;

    cudaFuncSetAttribute(gemm_kernel,
                         cudaFuncAttributeMaxDynamicSharedMemorySize, SMEM_TOTAL);

    conv_A_kernel<<<(int)(((size_t)NN * KTOT / 4) / 256), 256>>>(h0, behavior);
    conv_W_kernel<<<dim3(2048 / 32, 2048 / 32, 8), dim3(32, 8)>>>(
        Wi_h, Wi_x, Wf_h, Wf_x, Wg_h, Wg_x, Wo_h, Wo_x);
    gemm_kernel<<<dim3(NTOT / 256, NN / 128), 256, SMEM_TOTAL>>>();

    const size_t total4 = (size_t)NN * FFD / 4;
    lstm_epilogue_kernel<<<(int)((total4 + 255) / 256), 256>>>(
        c0, hout, bi, bf, bg, bo);
}

// round 4
// speedup vs baseline: 8.3126x; 2.4836x over previous
#include <cuda_runtime.h>
#include <cuda_fp16.h>
#include <cstdint>
#include <math.h>

#define NN   4096
#define FFD  2048
#define NTOT 8192   // 4 gates x 2048, concatenated in N
#define KTOT 4096   // concat K: [h0 (2048) | behavior (2048)]

// ---------------- device scratch (no cudaMalloc allowed) -------------------
static __device__ __half g_A[(size_t)NN * KTOT];        // 33.5MB  A fp16
static __device__ __half g_W[(size_t)NTOT * KTOT];      // 67MB    W^T fp16, [n_global][k]
static __device__ float  g_z[(size_t)4 * NN * FFD];     // 134MB   gate pre-activations

// ---------------- helpers ---------------------------------------------------
__device__ __forceinline__ uint32_t smem_u32(const void* p) {
    uint32_t a;
    asm("{ .reg .u64 t; cvta.to.shared.u64 t, %1; cvt.u32.u64 %0, t; }"
        : "=r"(a) : "l"(p));
    return a;
}
__device__ __forceinline__ void cpa16(uint32_t s, const void* g) {
    asm volatile("cp.async.cg.shared.global [%0], [%1], 16;" :: "r"(s), "l"(g));
}
#define CPA_COMMIT() asm volatile("cp.async.commit_group;" ::: "memory")
#define CPA_WAIT3()  asm volatile("cp.async.wait_group 3;" ::: "memory")

__device__ __forceinline__ void ldsm4(uint32_t* r, uint32_t addr) {
    asm volatile("ldmatrix.sync.aligned.m8n8.x4.shared.b16 {%0,%1,%2,%3}, [%4];"
                 : "=r"(r[0]), "=r"(r[1]), "=r"(r[2]), "=r"(r[3]) : "r"(addr));
}
__device__ __forceinline__ void mma16816(float* c, const uint32_t* a, const uint32_t* b) {
    asm volatile("mma.sync.aligned.m16n8k16.row.col.f32.f16.f16.f32 "
                 "{%0,%1,%2,%3}, {%4,%5,%6,%7}, {%8,%9}, {%0,%1,%2,%3};"
                 : "+f"(c[0]), "+f"(c[1]), "+f"(c[2]), "+f"(c[3])
                 : "r"(a[0]), "r"(a[1]), "r"(a[2]), "r"(a[3]),
                   "r"(b[0]), "r"(b[1]));
}

// ---------------- pre-pass 1: A = [h0 | behavior] -> fp16 -------------------
__global__ __launch_bounds__(256)
void conv_A_kernel(const float* __restrict__ h0, const float* __restrict__ beh) {
    size_t e = ((size_t)blockIdx.x * 256 + threadIdx.x) * 4;
    int m = (int)(e >> 12);
    int k = (int)(e & 4095);
    const float* src = (k < 2048) ? (h0 + (size_t)m * 2048 + k)
                                  : (beh + (size_t)m * 2048 + (k - 2048));
    float4 v = *(const float4*)src;
    __half2* dh = (__half2*)(g_A + e);
    dh[0] = __halves2half2(__float2half_rn(v.x), __float2half_rn(v.y));
    dh[1] = __halves2half2(__float2half_rn(v.z), __float2half_rn(v.w));
}

// ---------------- pre-pass 2: W transpose -> fp16 [n_global][k] -------------
// src matrices are [K=2048][N=2048] row-major; dst g_W[(g*2048+n)*4096 + isx*2048 + k]
__global__ __launch_bounds__(256)
void conv_W_kernel(const float* Wi_h, const float* Wi_x,
                   const float* Wf_h, const float* Wf_x,
                   const float* Wg_h, const float* Wg_x,
                   const float* Wo_h, const float* Wo_x) {
    const float* srcs[8] = {Wi_h, Wi_x, Wf_h, Wf_x, Wg_h, Wg_x, Wo_h, Wo_x};
    int z = blockIdx.z;
    int g = z >> 1, isx = z & 1;
    const float* __restrict__ src = srcs[z];

    __shared__ float t[32][33];
    int k0 = blockIdx.x * 32, n0 = blockIdx.y * 32;
    int tx = threadIdx.x, ty = threadIdx.y;
#pragma unroll
    for (int i = 0; i < 4; i++)
        t[ty + i * 8][tx] = src[(size_t)(k0 + ty + i * 8) * 2048 + n0 + tx];
    __syncthreads();
#pragma unroll
    for (int i = 0; i < 4; i++) {
        int n = n0 + ty + i * 8;
        int k = k0 + tx;
        float x = t[tx][ty + i * 8];
        g_W[((size_t)g * FFD + n) * KTOT + isx * 2048 + k] = __float2half_rn(x);
    }
}

// ---------------- main GEMM: z = A @ W^T (single-pass fp16) -----------------
// BM=128, BN=256, BK=64, 4 stages, 256 threads, warp tile 64x64 (2m x 4n)
static constexpr int A_OFF    = 0;        // 128 rows x 128B = 16KB
static constexpr int WP_OFF   = 16384;    // 256 rows x 128B = 32KB
static constexpr int STAGE_SZ = 49152;    // 48KB
static constexpr int SMEM_TOTAL = 4 * STAGE_SZ;  // 192KB

__device__ __forceinline__ void fill_stage(uint32_t sb, int m0, int n0, int kb, int tid) {
#pragma unroll
    for (int i = 0; i < 4; i++) {               // A: 1024 16B units
        int u = tid + i * 256;
        int row = u >> 3, cu = u & 7;
        uint32_t sw = (uint32_t)(row * 128 + ((cu ^ (row & 7)) << 4));
        size_t go = (size_t)(m0 + row) * KTOT + kb + cu * 8;
        cpa16(sb + A_OFF + sw, g_A + go);
    }
#pragma unroll
    for (int i = 0; i < 8; i++) {               // W: 2048 16B units
        int u = tid + i * 256;
        int row = u >> 3, cu = u & 7;
        uint32_t sw = (uint32_t)(row * 128 + ((cu ^ (row & 7)) << 4));
        size_t go = (size_t)(n0 + row) * KTOT + kb + cu * 8;
        cpa16(sb + WP_OFF + sw, g_W + go);
    }
}

__global__ __launch_bounds__(256, 1)
void gemm_kernel() {
    extern __shared__ __align__(1024) char smem[];
    const uint32_t base = smem_u32(smem);
    const int tid = threadIdx.x;
    const int wid = tid >> 5;
    const int lane = tid & 31;
    const int warp_m = wid & 1;    // 2 warps over M (64 rows each)
    const int warp_n = wid >> 1;   // 4 warps over N (64 cols each)
    const int m0 = blockIdx.y * 128;
    const int n0 = blockIdx.x * 256;

    const int quad = lane >> 3, rr = lane & 7;
    const int rowA_base = warp_m * 64 + (quad & 1) * 8 + rr;  // + mi*16
    const int chA = quad >> 1;
    const int rowB_base = warp_n * 64 + (quad >> 1) * 8 + rr; // + nh*16
    const int chB = quad & 1;

    float acc[4][8][4];
#pragma unroll
    for (int mi = 0; mi < 4; mi++)
#pragma unroll
        for (int ni = 0; ni < 8; ni++)
#pragma unroll
            for (int q = 0; q < 4; q++) acc[mi][ni][q] = 0.0f;

    // prologue: chunks 0,1,2
    fill_stage(base + 0 * STAGE_SZ, m0, n0, 0, tid);   CPA_COMMIT();
    fill_stage(base + 1 * STAGE_SZ, m0, n0, 64, tid);  CPA_COMMIT();
    fill_stage(base + 2 * STAGE_SZ, m0, n0, 128, tid); CPA_COMMIT();

    const int NCH = KTOT / 64;  // 64
#pragma unroll 1
    for (int c = 0; c < NCH; c++) {
        if (c + 3 < NCH)
            fill_stage(base + ((c + 3) & 3) * STAGE_SZ, m0, n0, (c + 3) * 64, tid);
        CPA_COMMIT();
        CPA_WAIT3();
        __syncthreads();

        const uint32_t sb = base + (c & 3) * STAGE_SZ;
        const uint32_t Ab = sb + A_OFF, Wb = sb + WP_OFF;

#pragma unroll
        for (int ks = 0; ks < 4; ks++) {
            uint32_t b[16], a[16];
#pragma unroll
            for (int nh = 0; nh < 4; nh++) {
                int row = rowB_base + nh * 16;
                int u = ks * 2 + chB;
                ldsm4(&b[nh * 4], Wb + row * 128 + ((u ^ (row & 7)) << 4));
            }
#pragma unroll
            for (int mi = 0; mi < 4; mi++) {
                int row = rowA_base + mi * 16;
                int u = ks * 2 + chA;
                ldsm4(&a[mi * 4], Ab + row * 128 + ((u ^ (row & 7)) << 4));
            }
#pragma unroll
            for (int mi = 0; mi < 4; mi++)
#pragma unroll
                for (int ni = 0; ni < 8; ni++)
                    mma16816(acc[mi][ni], &a[mi * 4],
                             &b[(ni >> 1) * 4 + (ni & 1) * 2]);
        }
        __syncthreads();
    }

    // ---- store z tile (raw pre-activation, bias added in epilogue) ----
    const int gate = n0 >> 11;
    float* __restrict__ Z = g_z + (size_t)gate * NN * FFD;
    const int ncol0 = (n0 & 2047) + warp_n * 64 + (lane & 3) * 2;
    const int row0  = m0 + warp_m * 64 + (lane >> 2);
#pragma unroll
    for (int mi = 0; mi < 4; mi++) {
        int r = row0 + mi * 16;
#pragma unroll
        for (int ni = 0; ni < 8; ni++) {
            int cc = ncol0 + ni * 8;
            *(float2*)(Z + (size_t)r * FFD + cc) =
                make_float2(acc[mi][ni][0], acc[mi][ni][1]);
            *(float2*)(Z + (size_t)(r + 8) * FFD + cc) =
                make_float2(acc[mi][ni][2], acc[mi][ni][3]);
        }
    }
}

// ---------------- LSTM elementwise epilogue ---------------------------------
__global__ __launch_bounds__(256)
void lstm_epilogue_kernel(const float* __restrict__ c0, float* __restrict__ h,
                          const float* __restrict__ bi, const float* __restrict__ bf,
                          const float* __restrict__ bg, const float* __restrict__ bo)
{
    size_t idx = (size_t)blockIdx.x * blockDim.x + threadIdx.x;  // float4 index
    size_t e = idx * 4;
    int col = (int)(e & (FFD - 1));

    const size_t GS = (size_t)NN * FFD;
    float4 zi = *(const float4*)(g_z + 0 * GS + e);
    float4 zf = *(const float4*)(g_z + 1 * GS + e);
    float4 zg = *(const float4*)(g_z + 2 * GS + e);
    float4 zo = *(const float4*)(g_z + 3 * GS + e);
    float4 bvi = *(const float4*)(bi + col);
    float4 bvf = *(const float4*)(bf + col);
    float4 bvg = *(const float4*)(bg + col);
    float4 bvo = *(const float4*)(bo + col);
    float4 c0v = *(const float4*)(c0 + e);

    float vi[4] = {zi.x + bvi.x, zi.y + bvi.y, zi.z + bvi.z, zi.w + bvi.w};
    float vf[4] = {zf.x + bvf.x, zf.y + bvf.y, zf.z + bvf.z, zf.w + bvf.w};
    float vg[4] = {zg.x + bvg.x, zg.y + bvg.y, zg.z + bvg.z, zg.w + bvg.w};
    float vo[4] = {zo.x + bvo.x, zo.y + bvo.y, zo.z + bvo.z, zo.w + bvo.w};
    float cv[4] = {c0v.x, c0v.y, c0v.z, c0v.w};

    float out[4];
#pragma unroll
    for (int j = 0; j < 4; j++) {
        float ig = 1.0f / (1.0f + expf(-vi[j]));
        float fg = 1.0f / (1.0f + expf(-vf[j]));
        float gg = tanhf(vg[j]);
        float og = 1.0f / (1.0f + expf(-vo[j]));
        float cc = fg * cv[j] + ig * gg;
        out[j] = og * tanhf(cc);
    }
    float4 o4 = make_float4(out[0], out[1], out[2], out[3]);
    *(float4*)(h + e) = o4;
}

// ---------------- kernel_launch ---------------------------------------------
// inputs: behavior, h0, c0, Wi_h, Wi_x, bi, Wf_h, Wf_x, bf, Wg_h, Wg_x, bg,
//         Wo_h, Wo_x, bo
extern "C" void kernel_launch(void* const* d_in, const int* in_sizes, int n_in,
                              void* d_out, int out_size)
{
    const float* behavior = (const float*)d_in[0];
    const float* h0       = (const float*)d_in[1];
    const float* c0       = (const float*)d_in[2];
    const float* Wi_h = (const float*)d_in[3];
    const float* Wi_x = (const float*)d_in[4];
    const float* bi   = (const float*)d_in[5];
    const float* Wf_h = (const float*)d_in[6];
    const float* Wf_x = (const float*)d_in[7];
    const float* bf   = (const float*)d_in[8];
    const float* Wg_h = (const float*)d_in[9];
    const float* Wg_x = (const float*)d_in[10];
    const float* bg   = (const float*)d_in[11];
    const float* Wo_h = (const float*)d_in[12];
    const float* Wo_x = (const float*)d_in[13];
    const float* bo   = (const float*)d_in[14];
    float* hout = (float*)d_out;

    cudaFuncSetAttribute(gemm_kernel,
                         cudaFuncAttributeMaxDynamicSharedMemorySize, SMEM_TOTAL);

    conv_A_kernel<<<(int)(((size_t)NN * KTOT / 4) / 256), 256>>>(h0, behavior);
    conv_W_kernel<<<dim3(2048 / 32, 2048 / 32, 8), dim3(32, 8)>>>(
        Wi_h, Wi_x, Wf_h, Wf_x, Wg_h, Wg_x, Wo_h, Wo_x);
    gemm_kernel<<<dim3(NTOT / 256, NN / 128), 256, SMEM_TOTAL>>>();

    const size_t total4 = (size_t)NN * FFD / 4;
    lstm_epilogue_kernel<<<(int)((total4 + 255) / 256), 256>>>(
        c0, hout, bi, bf, bg, bo);
}

// round 5
// speedup vs baseline: 8.4294x; 1.0140x over previous
#include <cuda_runtime.h>
#include <cuda_fp16.h>
#include <cstdint>
#include <math.h>

#define NN   4096
#define FFD  2048
#define KTOT 4096   // concat K: [h0 (2048) | behavior (2048)]

// ---------------- device scratch (no cudaMalloc allowed) -------------------
static __device__ __half g_A[(size_t)NN * KTOT];              // 33.5MB  A fp16
static __device__ __half g_W[(size_t)4 * FFD * KTOT];         // 67MB    W^T fp16 [g*FFD+n][k]

// ---------------- helpers ---------------------------------------------------
__device__ __forceinline__ uint32_t smem_u32(const void* p) {
    uint32_t a;
    asm("{ .reg .u64 t; cvta.to.shared.u64 t, %1; cvt.u32.u64 %0, t; }"
        : "=r"(a) : "l"(p));
    return a;
}
__device__ __forceinline__ void cpa16(uint32_t s, const void* g) {
    asm volatile("cp.async.cg.shared.global [%0], [%1], 16;" :: "r"(s), "l"(g));
}
#define CPA_COMMIT() asm volatile("cp.async.commit_group;" ::: "memory")
#define CPA_WAIT3()  asm volatile("cp.async.wait_group 3;" ::: "memory")

__device__ __forceinline__ void ldsm4(uint32_t* r, uint32_t addr) {
    asm volatile("ldmatrix.sync.aligned.m8n8.x4.shared.b16 {%0,%1,%2,%3}, [%4];"
                 : "=r"(r[0]), "=r"(r[1]), "=r"(r[2]), "=r"(r[3]) : "r"(addr));
}
__device__ __forceinline__ void mma16816(float* c, const uint32_t* a, const uint32_t* b) {
    asm volatile("mma.sync.aligned.m16n8k16.row.col.f32.f16.f16.f32 "
                 "{%0,%1,%2,%3}, {%4,%5,%6,%7}, {%8,%9}, {%0,%1,%2,%3};"
                 : "+f"(c[0]), "+f"(c[1]), "+f"(c[2]), "+f"(c[3])
                 : "r"(a[0]), "r"(a[1]), "r"(a[2]), "r"(a[3]),
                   "r"(b[0]), "r"(b[1]));
}

// ---------------- pre-pass 1: A = [h0 | behavior] -> fp16 -------------------
__global__ __launch_bounds__(256)
void conv_A_kernel(const float* __restrict__ h0, const float* __restrict__ beh) {
    size_t e = ((size_t)blockIdx.x * 256 + threadIdx.x) * 4;
    int m = (int)(e >> 12);
    int k = (int)(e & 4095);
    const float* src = (k < 2048) ? (h0 + (size_t)m * 2048 + k)
                                  : (beh + (size_t)m * 2048 + (k - 2048));
    float4 v = *(const float4*)src;
    __half2* dh = (__half2*)(g_A + e);
    dh[0] = __halves2half2(__float2half_rn(v.x), __float2half_rn(v.y));
    dh[1] = __halves2half2(__float2half_rn(v.z), __float2half_rn(v.w));
}

// ---------------- pre-pass 2: W transpose -> fp16 [g*FFD+n][k] --------------
__global__ __launch_bounds__(256)
void conv_W_kernel(const float* Wi_h, const float* Wi_x,
                   const float* Wf_h, const float* Wf_x,
                   const float* Wg_h, const float* Wg_x,
                   const float* Wo_h, const float* Wo_x) {
    const float* srcs[8] = {Wi_h, Wi_x, Wf_h, Wf_x, Wg_h, Wg_x, Wo_h, Wo_x};
    int z = blockIdx.z;
    int g = z >> 1, isx = z & 1;
    const float* __restrict__ src = srcs[z];

    __shared__ float t[32][33];
    int k0 = blockIdx.x * 32, n0 = blockIdx.y * 32;
    int tx = threadIdx.x, ty = threadIdx.y;
#pragma unroll
    for (int i = 0; i < 4; i++)
        t[ty + i * 8][tx] = src[(size_t)(k0 + ty + i * 8) * 2048 + n0 + tx];
    __syncthreads();
#pragma unroll
    for (int i = 0; i < 4; i++) {
        int n = n0 + ty + i * 8;
        int k = k0 + tx;
        float x = t[tx][ty + i * 8];
        g_W[((size_t)g * FFD + n) * KTOT + isx * 2048 + k] = __float2half_rn(x);
    }
}

// ---------------- fused 4-gate GEMM + LSTM epilogue -------------------------
// BM=128, BN=64 per gate (x4 gates), BK=64, 4 stages, 512 threads.
// 16 warps: warp_m in {0..3} (32 rows), warp_n in {0..3} (16 cols).
// Per warp per gate: 32x16 -> mi=2, ni=2. acc[4][2][2][4] = 64 floats.
static constexpr int A_OFF    = 0;        // 128 rows x 128B = 16KB
static constexpr int WP_OFF   = 16384;    // 4 gates x 64 rows x 128B = 32KB
static constexpr int STAGE_SZ = 49152;    // 48KB
static constexpr int SMEM_TOTAL = 4 * STAGE_SZ;  // 192KB

__device__ __forceinline__ void fill_stage(uint32_t sb, int m0, int n0, int kb, int tid) {
#pragma unroll
    for (int i = 0; i < 2; i++) {               // A: 1024 16B units
        int u = tid + i * 512;
        int row = u >> 3, cu = u & 7;
        uint32_t sw = (uint32_t)(row * 128 + ((cu ^ (row & 7)) << 4));
        size_t go = (size_t)(m0 + row) * KTOT + kb + cu * 8;
        cpa16(sb + A_OFF + sw, g_A + go);
    }
#pragma unroll
    for (int i = 0; i < 4; i++) {               // W: 2048 16B units (4 gates x 64 rows)
        int u = tid + i * 512;
        int row = u >> 3, cu = u & 7;           // row 0..255: gate = row>>6, n = row&63
        uint32_t sw = (uint32_t)(row * 128 + ((cu ^ (row & 7)) << 4));
        size_t go = ((size_t)(row >> 6) * FFD + n0 + (row & 63)) * KTOT + kb + cu * 8;
        cpa16(sb + WP_OFF + sw, g_W + go);
    }
}

__global__ __launch_bounds__(512, 1)
void lstm_gemm_kernel(const float* __restrict__ c0, float* __restrict__ hout,
                      const float* __restrict__ bi, const float* __restrict__ bf,
                      const float* __restrict__ bg, const float* __restrict__ bo)
{
    extern __shared__ __align__(1024) char smem[];
    const uint32_t base = smem_u32(smem);
    const int tid = threadIdx.x;
    const int wid = tid >> 5;
    const int lane = tid & 31;
    const int warp_m = wid & 3;    // 4 warps over M (32 rows each)
    const int warp_n = wid >> 2;   // 4 warps over N (16 cols each)
    const int m0 = blockIdx.y * 128;
    const int n0 = blockIdx.x * 64;

    const int quad = lane >> 3, rr = lane & 7;
    const int rowA_base = warp_m * 32 + (quad & 1) * 8 + rr;   // + mi*16
    const int chA = quad >> 1;
    const int rowB_base = warp_n * 16 + (quad >> 1) * 8 + rr;  // within 64-row gate slab
    const int chB = quad & 1;

    float acc[4][2][2][4];
#pragma unroll
    for (int g = 0; g < 4; g++)
#pragma unroll
        for (int mi = 0; mi < 2; mi++)
#pragma unroll
            for (int ni = 0; ni < 2; ni++)
#pragma unroll
                for (int q = 0; q < 4; q++) acc[g][mi][ni][q] = 0.0f;

    // prologue: chunks 0,1,2
    fill_stage(base + 0 * STAGE_SZ, m0, n0, 0, tid);   CPA_COMMIT();
    fill_stage(base + 1 * STAGE_SZ, m0, n0, 64, tid);  CPA_COMMIT();
    fill_stage(base + 2 * STAGE_SZ, m0, n0, 128, tid); CPA_COMMIT();

    const int NCH = KTOT / 64;  // 64
#pragma unroll 1
    for (int c = 0; c < NCH; c++) {
        if (c + 3 < NCH)
            fill_stage(base + ((c + 3) & 3) * STAGE_SZ, m0, n0, (c + 3) * 64, tid);
        CPA_COMMIT();
        CPA_WAIT3();
        __syncthreads();

        const uint32_t sb = base + (c & 3) * STAGE_SZ;
        const uint32_t Ab = sb + A_OFF, Wb = sb + WP_OFF;

#pragma unroll
        for (int ks = 0; ks < 4; ks++) {
            uint32_t a[8], b[16];
#pragma unroll
            for (int mi = 0; mi < 2; mi++) {
                int row = rowA_base + mi * 16;
                int u = ks * 2 + chA;
                ldsm4(&a[mi * 4], Ab + row * 128 + ((u ^ (row & 7)) << 4));
            }
#pragma unroll
            for (int g = 0; g < 4; g++) {
                int row = g * 64 + rowB_base;   // smem row within W slab
                int u = ks * 2 + chB;
                ldsm4(&b[g * 4], Wb + row * 128 + ((u ^ (row & 7)) << 4));
            }
#pragma unroll
            for (int g = 0; g < 4; g++)
#pragma unroll
                for (int mi = 0; mi < 2; mi++)
#pragma unroll
                    for (int ni = 0; ni < 2; ni++)
                        mma16816(acc[g][mi][ni], &a[mi * 4], &b[g * 4 + ni * 2]);
        }
        __syncthreads();
    }

    // ---- fused LSTM epilogue: acc[g] all live in this thread for same (m,n)
    const int row0 = m0 + warp_m * 32 + (lane >> 2);
    const int col0 = n0 + warp_n * 16 + (lane & 3) * 2;

#pragma unroll
    for (int ni = 0; ni < 2; ni++) {
        const int cc = col0 + ni * 8;
        float2 b_i = *(const float2*)(bi + cc);
        float2 b_f = *(const float2*)(bf + cc);
        float2 b_g = *(const float2*)(bg + cc);
        float2 b_o = *(const float2*)(bo + cc);
#pragma unroll
        for (int mi = 0; mi < 2; mi++) {
#pragma unroll
            for (int half = 0; half < 2; half++) {   // q{0,1} row r, q{2,3} row r+8
                int r = row0 + mi * 16 + half * 8;
                float2 cv = *(const float2*)(c0 + (size_t)r * FFD + cc);
                float out[2];
#pragma unroll
                for (int q = 0; q < 2; q++) {
                    float vi = acc[0][mi][ni][half * 2 + q] + (q ? b_i.y : b_i.x);
                    float vf = acc[1][mi][ni][half * 2 + q] + (q ? b_f.y : b_f.x);
                    float vg = acc[2][mi][ni][half * 2 + q] + (q ? b_g.y : b_g.x);
                    float vo = acc[3][mi][ni][half * 2 + q] + (q ? b_o.y : b_o.x);
                    float ig = 1.0f / (1.0f + expf(-vi));
                    float fg = 1.0f / (1.0f + expf(-vf));
                    float gg = tanhf(vg);
                    float og = 1.0f / (1.0f + expf(-vo));
                    float ccell = fg * (q ? cv.y : cv.x) + ig * gg;
                    out[q] = og * tanhf(ccell);
                }
                *(float2*)(hout + (size_t)r * FFD + cc) = make_float2(out[0], out[1]);
            }
        }
    }
}

// ---------------- kernel_launch ---------------------------------------------
// inputs: behavior, h0, c0, Wi_h, Wi_x, bi, Wf_h, Wf_x, bf, Wg_h, Wg_x, bg,
//         Wo_h, Wo_x, bo
extern "C" void kernel_launch(void* const* d_in, const int* in_sizes, int n_in,
                              void* d_out, int out_size)
{
    const float* behavior = (const float*)d_in[0];
    const float* h0       = (const float*)d_in[1];
    const float* c0       = (const float*)d_in[2];
    const float* Wi_h = (const float*)d_in[3];
    const float* Wi_x = (const float*)d_in[4];
    const float* bi   = (const float*)d_in[5];
    const float* Wf_h = (const float*)d_in[6];
    const float* Wf_x = (const float*)d_in[7];
    const float* bf   = (const float*)d_in[8];
    const float* Wg_h = (const float*)d_in[9];
    const float* Wg_x = (const float*)d_in[10];
    const float* bg   = (const float*)d_in[11];
    const float* Wo_h = (const float*)d_in[12];
    const float* Wo_x = (const float*)d_in[13];
    const float* bo   = (const float*)d_in[14];
    float* hout = (float*)d_out;

    cudaFuncSetAttribute(lstm_gemm_kernel,
                         cudaFuncAttributeMaxDynamicSharedMemorySize, SMEM_TOTAL);

    conv_A_kernel<<<(int)(((size_t)NN * KTOT / 4) / 256), 256>>>(h0, behavior);
    conv_W_kernel<<<dim3(2048 / 32, 2048 / 32, 8), dim3(32, 8)>>>(
        Wi_h, Wi_x, Wf_h, Wf_x, Wg_h, Wg_x, Wo_h, Wo_x);
    lstm_gemm_kernel<<<dim3(FFD / 64, NN / 128), 512, SMEM_TOTAL>>>(
        c0, hout, bi, bf, bg, bo);
}